// round 10
// baseline (speedup 1.0000x reference)
#include <cuda_runtime.h>
#include <cuda_fp16.h>
#include <math.h>
#include <stdint.h>

#define BB 4
#define DIM 192
#define C3 576
#define HF 256
#define WF 256
#define HP 128
#define WP 128
#define NPX 16384
#define NHEADS 6
#define CPH 32

// scratch (device globals: allocation-free)
__device__ float  g_P[BB * C3 * HP * WP];      // pooled qkv (fp32)
__device__ float  g_D[BB * C3 * HP * WP];      // after dwconv (fp32, all channels)
__device__ __half g_Dh[BB * 384 * HP * WP];    // after dwconv, q+k only, fp16
__device__ __half g_low[BB * DIM * NPX];       // gelu(out) low-res, fp16
__device__ float  g_G[BB * NHEADS * CPH * CPH];
__device__ float  g_A[BB * NHEADS * CPH * CPH];
__device__ float  g_sq[BB * NHEADS * CPH];
__device__ float  g_sk[BB * NHEADS * CPH];

// ============================ MMA helpers ==================================
__device__ __forceinline__ void mma_f16(float* d, const uint32_t* a, const uint32_t* b) {
    asm volatile(
        "mma.sync.aligned.m16n8k16.row.col.f32.f16.f16.f32 "
        "{%0,%1,%2,%3}, {%4,%5,%6,%7}, {%8,%9}, {%0,%1,%2,%3};"
        : "+f"(d[0]), "+f"(d[1]), "+f"(d[2]), "+f"(d[3])
        : "r"(a[0]), "r"(a[1]), "r"(a[2]), "r"(a[3]), "r"(b[0]), "r"(b[1]));
}
__device__ __forceinline__ void ldsm4(uint32_t* r, uint32_t a) {
    asm volatile("ldmatrix.sync.aligned.m8n8.x4.shared.b16 {%0,%1,%2,%3}, [%4];"
        : "=r"(r[0]), "=r"(r[1]), "=r"(r[2]), "=r"(r[3]) : "r"(a));
}
__device__ __forceinline__ void ldsm2t(uint32_t* r, uint32_t a) {
    asm volatile("ldmatrix.sync.aligned.m8n8.x2.trans.shared.b16 {%0,%1}, [%2];"
        : "=r"(r[0]), "=r"(r[1]) : "r"(a));
}
__device__ __forceinline__ uint32_t h2u(__half2 h) { return *(uint32_t*)&h; }

#define BS_PAD 136    // fp16 per B row (272B)
#define A_PITCH 200   // fp16 per A row (400B)

// ---------------------------------------------------------------------------
// K1: qkv 1x1 conv fp16 MMA + fused 2x2 maxpool. B (x tile) resident,
// A tile (64co x 192k) resident per co-tile -> 12 barrier-free k-steps.
// smem: Bs 192x136 (52224B) | As 64x200 (25600B) | ps 64x36 f32 (9216B).
// ---------------------------------------------------------------------------
#define K1_AOFF 52224
#define K1_POFF (52224 + 25600)
#define K1_SMEM (K1_POFF + 9216)

__global__ void __launch_bounds__(256, 2) k1_mma(const float* __restrict__ x,
                                                 const float* __restrict__ w) {
    extern __shared__ __align__(16) char smem[];
    __half* Bs = (__half*)smem;
    __half* As = (__half*)(smem + K1_AOFF);
    float*  ps = (float*)(smem + K1_POFF);
    uint32_t sbase;
    asm("{ .reg .u64 t; cvta.to.shared.u64 t, %1; cvt.u32.u64 %0, t; }"
        : "=r"(sbase) : "l"(smem));

    const int tid = threadIdx.x;
    const int ctaN = blockIdx.x, b = blockIdx.z;
    const int lane = tid & 31, warp = tid >> 5;
    const int warpM = warp >> 2, warpN = warp & 3;
    const int g = lane >> 2, t4 = lane & 3;

    const int pi = ctaN >> 2;
    const int pj0 = (ctaN & 3) * 32;

    // resident B: n = 4*j + 2*r + e (pooled-quad interleave), fp16
    {
        const float* xb = x + (size_t)b * DIM * (HF * WF)
                            + (size_t)(2 * pi) * WF + 2 * pj0;
        for (int idx = tid; idx < 192 * 64; idx += 256) {
            int kk = idx >> 6, rem = idx & 63;
            int r = rem >> 5, j = rem & 31;
            float2 v = *(const float2*)&xb[(size_t)kk * (HF * WF) + (size_t)r * WF + 2 * j];
            *(__half2*)&Bs[kk * BS_PAD + 4 * j + 2 * r] = __floats2half2_rn(v.x, v.y);
        }
    }

    const uint32_t aRow = sbase + K1_AOFF
        + (uint32_t)(warpM * 32 + (lane & 15)) * 400 + ((lane >> 4) << 4);
    const uint32_t bRow = sbase
        + (uint32_t)((lane & 7) + (((lane >> 3) & 1) << 3)) * (BS_PAD * 2)
        + (uint32_t)warpN * 64;
    __syncthreads();

    for (int mt9 = 0; mt9 < 9; mt9++) {
        const int co0 = mt9 * 64;
        // A tile: 64 co x 192 k, fp32->fp16, single buffer
        for (int idx = tid; idx < 1536; idx += 256) {
            int co = idx / 24, kg = idx % 24;
            const float* src = w + (size_t)(co0 + co) * DIM + kg * 8;
            float4 f0 = *(const float4*)src;
            float4 f1 = *(const float4*)(src + 4);
            uint4 u;
            u.x = h2u(__floats2half2_rn(f0.x, f0.y));
            u.y = h2u(__floats2half2_rn(f0.z, f0.w));
            u.z = h2u(__floats2half2_rn(f1.x, f1.y));
            u.w = h2u(__floats2half2_rn(f1.z, f1.w));
            *(uint4*)&As[co * A_PITCH + kg * 8] = u;
        }
        __syncthreads();

        float acc[2][4][4];
#pragma unroll
        for (int i0 = 0; i0 < 2; i0++)
#pragma unroll
            for (int i1 = 0; i1 < 4; i1++)
#pragma unroll
                for (int i2 = 0; i2 < 4; i2++) acc[i0][i1][i2] = 0.f;

#pragma unroll
        for (int ks = 0; ks < 12; ks++) {
            uint32_t afr[2][4], bfr[4][2];
            ldsm4(afr[0], aRow + ks * 32);
            ldsm4(afr[1], aRow + 16 * 400 + ks * 32);
#pragma unroll
            for (int nt = 0; nt < 4; nt++)
                ldsm2t(bfr[nt], bRow + (uint32_t)ks * (16 * BS_PAD * 2) + nt * 16);
#pragma unroll
            for (int mt = 0; mt < 2; mt++)
#pragma unroll
                for (int nt = 0; nt < 4; nt++)
                    mma_f16(acc[mt][nt], afr[mt], bfr[nt]);
        }

        // epilogue: 2x2 pool -> stage -> store
#pragma unroll
        for (int mt = 0; mt < 2; mt++)
#pragma unroll
            for (int nt = 0; nt < 4; nt++) {
                float m01 = fmaxf(acc[mt][nt][0], acc[mt][nt][1]);
                float m23 = fmaxf(acc[mt][nt][2], acc[mt][nt][3]);
                m01 = fmaxf(m01, __shfl_xor_sync(0xffffffffu, m01, 1));
                m23 = fmaxf(m23, __shfl_xor_sync(0xffffffffu, m23, 1));
                if (!(t4 & 1)) {
                    int pj = warpN * 8 + nt * 2 + (t4 >> 1);
                    int co = warpM * 32 + mt * 16 + g;
                    ps[co * 36 + pj] = m01;
                    ps[(co + 8) * 36 + pj] = m23;
                }
            }
        __syncthreads();
        for (int idx = tid; idx < 64 * 8; idx += 256) {
            int row = idx >> 3, c4 = idx & 7;
            float4 v = *(const float4*)&ps[row * 36 + c4 * 4];
            *(float4*)&g_P[(((size_t)b * C3 + co0 + row) * HP + pi) * WP + pj0 + c4 * 4] = v;
        }
        __syncthreads();
    }
}

// ---------------------------------------------------------------------------
// K7: proj 1x1 conv at LOW-res fp16 MMA (A resident per co-tile) + nearest-x2.
// smem: Bs 52224 | As 25600 | ps 64x132 f32 (33792B) = 111616B.
// ---------------------------------------------------------------------------
#define K7_AOFF 52224
#define K7_POFF (52224 + 25600)
#define K7_SMEM (K7_POFF + 33792)

__global__ void __launch_bounds__(256, 2) k7_mma(const float* __restrict__ w,
                                                 float* __restrict__ out) {
    extern __shared__ __align__(16) char smem[];
    __half* Bs = (__half*)smem;
    __half* As = (__half*)(smem + K7_AOFF);
    float*  ps = (float*)(smem + K7_POFF);
    uint32_t sbase;
    asm("{ .reg .u64 t; cvta.to.shared.u64 t, %1; cvt.u32.u64 %0, t; }"
        : "=r"(sbase) : "l"(smem));

    const int tid = threadIdx.x;
    const int ctaN = blockIdx.x, b = blockIdx.z;   // low-res row
    const int lane = tid & 31, warp = tid >> 5;
    const int warpM = warp >> 2, warpN = warp & 3;
    const int g = lane >> 2, t4 = lane & 3;

    // resident B: one low-res row, 192k x 128px fp16 passthrough
    {
        const __half* xb = g_low + (size_t)b * DIM * NPX + (size_t)ctaN * 128;
        for (int idx = tid; idx < 192 * 16; idx += 256) {
            int kk = idx >> 4, jg = idx & 15;
            *(uint4*)&Bs[kk * BS_PAD + jg * 8] =
                *(const uint4*)&xb[(size_t)kk * NPX + jg * 8];
        }
    }

    const uint32_t aRow = sbase + K7_AOFF
        + (uint32_t)(warpM * 32 + (lane & 15)) * 400 + ((lane >> 4) << 4);
    const uint32_t bRow = sbase
        + (uint32_t)((lane & 7) + (((lane >> 3) & 1) << 3)) * (BS_PAD * 2)
        + (uint32_t)warpN * 64;
    __syncthreads();

    for (int mt3 = 0; mt3 < 3; mt3++) {
        const int co0 = mt3 * 64;
        for (int idx = tid; idx < 1536; idx += 256) {
            int co = idx / 24, kg = idx % 24;
            const float* src = w + (size_t)(co0 + co) * DIM + kg * 8;
            float4 f0 = *(const float4*)src;
            float4 f1 = *(const float4*)(src + 4);
            uint4 u;
            u.x = h2u(__floats2half2_rn(f0.x, f0.y));
            u.y = h2u(__floats2half2_rn(f0.z, f0.w));
            u.z = h2u(__floats2half2_rn(f1.x, f1.y));
            u.w = h2u(__floats2half2_rn(f1.z, f1.w));
            *(uint4*)&As[co * A_PITCH + kg * 8] = u;
        }
        __syncthreads();

        float acc[2][4][4];
#pragma unroll
        for (int i0 = 0; i0 < 2; i0++)
#pragma unroll
            for (int i1 = 0; i1 < 4; i1++)
#pragma unroll
                for (int i2 = 0; i2 < 4; i2++) acc[i0][i1][i2] = 0.f;

#pragma unroll
        for (int ks = 0; ks < 12; ks++) {
            uint32_t afr[2][4], bfr[4][2];
            ldsm4(afr[0], aRow + ks * 32);
            ldsm4(afr[1], aRow + 16 * 400 + ks * 32);
#pragma unroll
            for (int nt = 0; nt < 4; nt++)
                ldsm2t(bfr[nt], bRow + (uint32_t)ks * (16 * BS_PAD * 2) + nt * 16);
#pragma unroll
            for (int mt = 0; mt < 2; mt++)
#pragma unroll
                for (int nt = 0; nt < 4; nt++)
                    mma_f16(acc[mt][nt], afr[mt], bfr[nt]);
        }

        // stage 64x128 tile, duplicate-write to full res
#pragma unroll
        for (int mt = 0; mt < 2; mt++)
#pragma unroll
            for (int nt = 0; nt < 4; nt++) {
                int co = warpM * 32 + mt * 16 + g;
                int n = warpN * 32 + nt * 8 + 2 * t4;
                *(float2*)&ps[co * 132 + n] = make_float2(acc[mt][nt][0], acc[mt][nt][1]);
                *(float2*)&ps[(co + 8) * 132 + n] = make_float2(acc[mt][nt][2], acc[mt][nt][3]);
            }
        __syncthreads();
        for (int idx = tid; idx < 64 * 32; idx += 256) {
            int row = idx >> 5, c4 = idx & 31;
            float4 s = *(const float4*)&ps[row * 132 + c4 * 4];
            float* ob = out + (size_t)(b * DIM + co0 + row) * (HF * WF)
                            + (size_t)(2 * ctaN) * WF + c4 * 8;
            float4 lo = make_float4(s.x, s.x, s.y, s.y);
            float4 hi = make_float4(s.z, s.z, s.w, s.w);
            *(float4*)(ob + 0) = lo;
            *(float4*)(ob + 4) = hi;
            *(float4*)(ob + WF) = lo;
            *(float4*)(ob + WF + 4) = hi;
        }
        __syncthreads();
    }
}

// ---------------------------------------------------------------------------
// K2: depthwise 3x3 SAME (32 rows/block) + fp16 q/k side-write + fused norms.
// ---------------------------------------------------------------------------
__global__ void __launch_bounds__(256) k2_dw(const float* __restrict__ dw) {
    int strip = blockIdx.x, c = blockIdx.y, b = blockIdx.z;
    int i0 = strip * 32;
    int tid = threadIdx.x;
    int lane = tid & 31, warp = tid >> 5;
    __shared__ float s[34][132];
    __shared__ float red[8];
    const float* base = g_P + (size_t)(b * C3 + c) * HP * WP;
    for (int idx = tid; idx < 34 * 32; idx += 256) {
        int r = idx >> 5, c4 = idx & 31;
        int ri = i0 - 1 + r;
        float4 v = make_float4(0.f, 0.f, 0.f, 0.f);
        if (ri >= 0 && ri < HP) v = *(const float4*)&base[(size_t)ri * WP + c4 * 4];
        s[r][1 + c4 * 4 + 0] = v.x; s[r][1 + c4 * 4 + 1] = v.y;
        s[r][1 + c4 * 4 + 2] = v.z; s[r][1 + c4 * 4 + 3] = v.w;
    }
    if (tid < 34) { s[tid][0] = 0.f; s[tid][129] = 0.f; }
    __syncthreads();

    float k00 = dw[c * 9 + 0], k01 = dw[c * 9 + 1], k02 = dw[c * 9 + 2];
    float k10 = dw[c * 9 + 3], k11 = dw[c * 9 + 4], k12 = dw[c * 9 + 5];
    float k20 = dw[c * 9 + 6], k21 = dw[c * 9 + 7], k22 = dw[c * 9 + 8];

    int j = tid & 127;
    int r0 = (tid >> 7) * 16;
    const bool isqk = (c < 384);
    float a0 = s[r0][j],     a1 = s[r0][j + 1],     a2 = s[r0][j + 2];
    float b0 = s[r0 + 1][j], b1 = s[r0 + 1][j + 1], b2 = s[r0 + 1][j + 2];
    float*  ob  = g_D + ((size_t)(b * C3 + c) * HP + i0 + r0) * WP + j;
    __half* obh = g_Dh + ((size_t)(b * 384 + (isqk ? c : 0)) * HP + i0 + r0) * WP + j;
    float nrm = 0.f;
#pragma unroll
    for (int r = 0; r < 16; r++) {
        float c0 = s[r0 + r + 2][j], c1 = s[r0 + r + 2][j + 1], c2 = s[r0 + r + 2][j + 2];
        float acc = k00 * a0;
        acc = fmaf(k01, a1, acc); acc = fmaf(k02, a2, acc);
        acc = fmaf(k10, b0, acc); acc = fmaf(k11, b1, acc); acc = fmaf(k12, b2, acc);
        acc = fmaf(k20, c0, acc); acc = fmaf(k21, c1, acc); acc = fmaf(k22, c2, acc);
        ob[(size_t)r * WP] = acc;
        if (isqk) {
            __half hv = __float2half_rn(acc);
            obh[(size_t)r * WP] = hv;
            float hf = __half2float(hv);
            nrm = fmaf(hf, hf, nrm);
        }
        a0 = b0; a1 = b1; a2 = b2;
        b0 = c0; b1 = c1; b2 = c2;
    }
    // block-wide norm reduce (all threads share channel c)
#pragma unroll
    for (int o = 16; o; o >>= 1) nrm += __shfl_xor_sync(0xffffffffu, nrm, o);
    if (lane == 0) red[warp] = nrm;
    __syncthreads();
    if (tid == 0 && isqk) {
        float t = red[0] + red[1] + red[2] + red[3] + red[4] + red[5] + red[6] + red[7];
        float* dst = (c < 192)
            ? &g_sq[(b * NHEADS + (c >> 5)) * CPH + (c & 31)]
            : &g_sk[(b * NHEADS + ((c - 192) >> 5)) * CPH + ((c - 192) & 31)];
        atomicAdd(dst, t);
    }
}

__global__ void k_init() {
    int idx = blockIdx.x * blockDim.x + threadIdx.x;
    if (idx < BB * NHEADS * CPH * CPH) g_G[idx] = 0.f;
    if (idx < BB * NHEADS * CPH) { g_sq[idx] = 0.f; g_sk[idx] = 0.f; }
}

// ---------------------------------------------------------------------------
// K4: gram via fp16 MMA, fragments loaded DIRECTLY from global (no smem tile).
// grid (32 splits, 24 bh); warp handles full 32x32 over 64-pixel slice.
// ---------------------------------------------------------------------------
__global__ void __launch_bounds__(256) k4_mma() {
    const int split = blockIdx.x, bh = blockIdx.y;
    const int b = bh / NHEADS, h = bh % NHEADS;
    const int tid = threadIdx.x;
    const int lane = tid & 31, warp = tid >> 5;
    const int g = lane >> 2, cpair = (lane & 3) * 2;

    __shared__ float Gs[32][33];
    for (int idx = tid; idx < 32 * 33; idx += 256) (&Gs[0][0])[idx] = 0.f;
    __syncthreads();

    const __half* qb = g_Dh + (size_t)(b * 384 + h * CPH) * NPX;
    const __half* kb = g_Dh + (size_t)(b * 384 + 192 + h * CPH) * NPX;

    float acc[2][4][4];
#pragma unroll
    for (int i0 = 0; i0 < 2; i0++)
#pragma unroll
        for (int i1 = 0; i1 < 4; i1++)
#pragma unroll
            for (int i2 = 0; i2 < 4; i2++) acc[i0][i1][i2] = 0.f;

    const int n_base = (split * 8 + warp) * 64;
#pragma unroll
    for (int kt = 0; kt < 4; kt++) {
        const int n0 = n_base + kt * 16;
        uint32_t a[2][4], bb[4][2];
#pragma unroll
        for (int mt = 0; mt < 2; mt++) {
            const __half* qrow = qb + (size_t)(mt * 16 + g) * NPX + n0 + cpair;
            a[mt][0] = *(const uint32_t*)(qrow);
            a[mt][1] = *(const uint32_t*)(qrow + 8 * NPX);
            a[mt][2] = *(const uint32_t*)(qrow + 8);
            a[mt][3] = *(const uint32_t*)(qrow + 8 * NPX + 8);
        }
#pragma unroll
        for (int nt = 0; nt < 4; nt++) {
            const __half* krow = kb + (size_t)(nt * 8 + g) * NPX + n0 + cpair;
            bb[nt][0] = *(const uint32_t*)(krow);
            bb[nt][1] = *(const uint32_t*)(krow + 8);
        }
#pragma unroll
        for (int mt = 0; mt < 2; mt++)
#pragma unroll
            for (int nt = 0; nt < 4; nt++)
                mma_f16(acc[mt][nt], a[mt], bb[nt]);
    }
    // reduce across 8 warps in smem, then one global atomic pass
#pragma unroll
    for (int mt = 0; mt < 2; mt++)
#pragma unroll
        for (int nt = 0; nt < 4; nt++) {
            atomicAdd(&Gs[mt * 16 + g][nt * 8 + cpair],         acc[mt][nt][0]);
            atomicAdd(&Gs[mt * 16 + g][nt * 8 + cpair + 1],     acc[mt][nt][1]);
            atomicAdd(&Gs[mt * 16 + g + 8][nt * 8 + cpair],     acc[mt][nt][2]);
            atomicAdd(&Gs[mt * 16 + g + 8][nt * 8 + cpair + 1], acc[mt][nt][3]);
        }
    __syncthreads();
    for (int idx = tid; idx < 1024; idx += 256)
        atomicAdd(&g_G[(size_t)bh * 1024 + idx], Gs[idx >> 5][idx & 31]);
}

// ---------------------------------------------------------------------------
// K5: normalize gram -> attn, 4 top-k masked softmaxes fused into combined A.
// ---------------------------------------------------------------------------
__global__ void k5_softmax(const float* __restrict__ temp,
                           const float* __restrict__ a1p, const float* __restrict__ a2p,
                           const float* __restrict__ a3p, const float* __restrict__ a4p) {
    int bh = blockIdx.x;
    int h = bh % NHEADS;
    int tid = threadIdx.x;
    int warp = tid >> 5, d = tid & 31;
    float t = temp[h];
    float A1 = *a1p, A2 = *a2p, A3 = *a3p, A4 = *a4p;
    float rk = 1.f / fmaxf(sqrtf(g_sk[bh * CPH + d]), 1e-12f);
    for (int it = 0; it < 4; it++) {
        int c = warp * 4 + it;
        float rq = 1.f / fmaxf(sqrtf(g_sq[bh * CPH + c]), 1e-12f);
        float v = g_G[((size_t)bh * CPH + c) * CPH + d] * rq * rk * t;
        int rank = 0;
#pragma unroll
        for (int j = 0; j < 32; j++) {
            float vj = __shfl_sync(0xffffffffu, v, j);
            rank += (vj > v) || (vj == v && j < d);
        }
        float vmax = v;
#pragma unroll
        for (int o = 16; o; o >>= 1) vmax = fmaxf(vmax, __shfl_xor_sync(0xffffffffu, vmax, o));
        float e = expf(v - vmax);
        float e1 = rank < 16 ? e : 0.f;
        float e2 = rank < 21 ? e : 0.f;
        float e3 = rank < 24 ? e : 0.f;
        float e4 = rank < 25 ? e : 0.f;
#pragma unroll
        for (int o = 16; o; o >>= 1) {
            e1 += __shfl_xor_sync(0xffffffffu, e1, o);
            e2 += __shfl_xor_sync(0xffffffffu, e2, o);
            e3 += __shfl_xor_sync(0xffffffffu, e3, o);
            e4 += __shfl_xor_sync(0xffffffffu, e4, o);
        }
        float wgt = (rank < 16 ? A1 / e1 : 0.f) + (rank < 21 ? A2 / e2 : 0.f)
                  + (rank < 24 ? A3 / e3 : 0.f) + (rank < 25 ? A4 / e4 : 0.f);
        g_A[((size_t)bh * CPH + c) * CPH + d] = e * wgt;
    }
}

// ---------------------------------------------------------------------------
// K6: out_low = A @ v (fp32 exact), GELU, store fp16 g_low.
// ---------------------------------------------------------------------------
__global__ void __launch_bounds__(256) k6_apply() {
    int bh = blockIdx.y;
    int b = bh / NHEADS, h = bh % NHEADS;
    int tid = threadIdx.x;
    __shared__ float As[32][32];
    reinterpret_cast<float4*>(&As[0][0])[tid] =
        reinterpret_cast<const float4*>(&g_A[(size_t)bh * 1024])[tid];
    __syncthreads();
    int px = blockIdx.x * 256 + tid;
    const float* vb = g_D + (size_t)(b * C3 + 2 * DIM + h * CPH) * NPX + px;
    float acc[32];
#pragma unroll
    for (int c = 0; c < 32; c++) acc[c] = 0.f;
#pragma unroll 4
    for (int d = 0; d < 32; d++) {
        float vd = vb[(size_t)d * NPX];
#pragma unroll
        for (int c = 0; c < 32; c++) acc[c] = fmaf(As[c][d], vd, acc[c]);
    }
    __half* ob = g_low + (size_t)(b * DIM + h * CPH) * NPX + px;
#pragma unroll
    for (int c = 0; c < 32; c++) {
        float xg = acc[c];
        ob[(size_t)c * NPX] =
            __float2half_rn(0.5f * xg * (1.f + erff(xg * 0.70710678118654752f)));
    }
}

extern "C" void kernel_launch(void* const* d_in, const int* in_sizes, int n_in,
                              void* d_out, int out_size) {
    const float* x      = (const float*)d_in[0];
    const float* temp   = (const float*)d_in[1];
    const float* qkv_w  = (const float*)d_in[2];
    const float* dw_w   = (const float*)d_in[3];
    const float* proj_w = (const float*)d_in[4];
    const float* a1     = (const float*)d_in[5];
    const float* a2     = (const float*)d_in[6];
    const float* a3     = (const float*)d_in[7];
    const float* a4     = (const float*)d_in[8];
    float* out = (float*)d_out;

    cudaFuncSetAttribute(k1_mma, cudaFuncAttributeMaxDynamicSharedMemorySize, K1_SMEM);
    cudaFuncSetAttribute(k7_mma, cudaFuncAttributeMaxDynamicSharedMemorySize, K7_SMEM);

    k_init<<<96, 256>>>();
    k1_mma<<<dim3(512, 1, 4), 256, K1_SMEM>>>(x, qkv_w);
    k2_dw<<<dim3(4, 576, 4), 256>>>(dw_w);
    k4_mma<<<dim3(32, 24), 256>>>();
    k5_softmax<<<24, 256>>>(temp, a1, a2, a3, a4);
    k6_apply<<<dim3(64, 24), 256>>>();
    k7_mma<<<dim3(128, 1, 4), 256, K7_SMEM>>>(proj_w, out);
}

// round 14
// speedup vs baseline: 1.2868x; 1.2868x over previous
#include <cuda_runtime.h>
#include <cuda_fp16.h>
#include <math.h>
#include <stdint.h>

#define BB 4
#define DIM 192
#define C3 576
#define HF 256
#define WF 256
#define HP 128
#define WP 128
#define NPX 16384
#define NHEADS 6
#define CPH 32

// scratch (device globals: allocation-free)
__device__ float  g_P[BB * C3 * HP * WP];      // pooled qkv (fp32)
__device__ float  g_D[BB * C3 * HP * WP];      // after dwconv (fp32, all channels)
__device__ __half g_Dh[BB * 384 * HP * WP];    // after dwconv, q+k only, fp16
__device__ __half g_low[BB * DIM * NPX];       // gelu(out) low-res, fp16
__device__ __half g_wh[C3 * DIM];              // qkv_w fp16
__device__ __half g_pwh[DIM * DIM];            // proj_w fp16
__device__ float  g_G[BB * NHEADS * CPH * CPH];
__device__ float  g_A[BB * NHEADS * CPH * CPH];
__device__ float  g_sq[BB * NHEADS * CPH];
__device__ float  g_sk[BB * NHEADS * CPH];

// ============================ MMA / async helpers ==========================
__device__ __forceinline__ void mma_f16(float* d, const uint32_t* a, const uint32_t* b) {
    asm volatile(
        "mma.sync.aligned.m16n8k16.row.col.f32.f16.f16.f32 "
        "{%0,%1,%2,%3}, {%4,%5,%6,%7}, {%8,%9}, {%0,%1,%2,%3};"
        : "+f"(d[0]), "+f"(d[1]), "+f"(d[2]), "+f"(d[3])
        : "r"(a[0]), "r"(a[1]), "r"(a[2]), "r"(a[3]), "r"(b[0]), "r"(b[1]));
}
__device__ __forceinline__ void ldsm4(uint32_t* r, uint32_t a) {
    asm volatile("ldmatrix.sync.aligned.m8n8.x4.shared.b16 {%0,%1,%2,%3}, [%4];"
        : "=r"(r[0]), "=r"(r[1]), "=r"(r[2]), "=r"(r[3]) : "r"(a));
}
__device__ __forceinline__ void ldsm2t(uint32_t* r, uint32_t a) {
    asm volatile("ldmatrix.sync.aligned.m8n8.x2.trans.shared.b16 {%0,%1}, [%2];"
        : "=r"(r[0]), "=r"(r[1]) : "r"(a));
}
__device__ __forceinline__ uint32_t h2u(__half2 h) { return *(uint32_t*)&h; }
__device__ __forceinline__ void cp16(uint32_t dst, const void* src) {
    asm volatile("cp.async.cg.shared.global [%0], [%1], 16;" :: "r"(dst), "l"(src));
}
#define CP_COMMIT() asm volatile("cp.async.commit_group;" ::: "memory")
#define CP_WAIT(n)  asm volatile("cp.async.wait_group %0;" :: "n"(n) : "memory")

#define BS_PAD 136      // fp16 per B row (272B)
#define A_PITCH_B 400   // bytes per A row (192 fp16 = 384B + 16 pad)
#define A_TILE_B 25600  // 64 rows * 400B

// ---------------------------------------------------------------------------
// K0: convert weights fp32 -> fp16 once.
// ---------------------------------------------------------------------------
__global__ void k0_convert(const float* __restrict__ qkv_w,
                           const float* __restrict__ proj_w) {
    int i = blockIdx.x * blockDim.x + threadIdx.x;
    const int n1 = C3 * DIM / 4;          // 27648 float4s
    const int n2 = DIM * DIM / 4;         // 9216
    if (i < n1) {
        float4 f = *(const float4*)&qkv_w[i * 4];
        *(uint2*)&g_wh[i * 4] = make_uint2(h2u(__floats2half2_rn(f.x, f.y)),
                                           h2u(__floats2half2_rn(f.z, f.w)));
    } else if (i < n1 + n2) {
        int j = i - n1;
        float4 f = *(const float4*)&proj_w[j * 4];
        *(uint2*)&g_pwh[j * 4] = make_uint2(h2u(__floats2half2_rn(f.x, f.y)),
                                            h2u(__floats2half2_rn(f.z, f.w)));
    }
}

// ---------------------------------------------------------------------------
// K1: qkv 1x1 conv fp16 MMA + fused 2x2 maxpool. B (x tile) resident,
// A tiles cp.async double-buffered (prefetch co-tile mt+1 during tile mt MMA).
// smem: Bs 192x136 (52224B) | As 2x25600B | ps 64x36 f32 (9216B) = 112640B.
// ---------------------------------------------------------------------------
#define K1_AOFF 52224
#define K1_POFF (52224 + 2 * A_TILE_B)
#define K1_SMEM (K1_POFF + 9216)

__global__ void __launch_bounds__(256, 2) k1_mma(const float* __restrict__ x) {
    extern __shared__ __align__(16) char smem[];
    __half* Bs = (__half*)smem;
    float*  ps = (float*)(smem + K1_POFF);
    uint32_t sbase;
    asm("{ .reg .u64 t; cvta.to.shared.u64 t, %1; cvt.u32.u64 %0, t; }"
        : "=r"(sbase) : "l"(smem));

    const int tid = threadIdx.x;
    const int ctaN = blockIdx.x, b = blockIdx.z;
    const int lane = tid & 31, warp = tid >> 5;
    const int warpM = warp >> 2, warpN = warp & 3;
    const int g = lane >> 2, t4 = lane & 3;

    const int pi = ctaN >> 2;
    const int pj0 = (ctaN & 3) * 32;

    // thread's cp.async slice for A tiles (6 x 16B per thread)
    const int coA = tid / 24 * 4 + (tid % 24) / 6;   // unused simple mapping below
    (void)coA;

    // prefetch A tile 0 (co 0..63)
    {
        const uint32_t dst0 = sbase + K1_AOFF;
        for (int idx = tid; idx < 1536; idx += 256) {
            int co = idx / 24, kg = idx % 24;
            cp16(dst0 + co * A_PITCH_B + kg * 16, &g_wh[(size_t)co * DIM + kg * 8]);
        }
        CP_COMMIT();
    }

    // resident B: n = 4*j + 2*r + e (pooled-quad interleave), fp16
    {
        const float* xb = x + (size_t)b * DIM * (HF * WF)
                            + (size_t)(2 * pi) * WF + 2 * pj0;
        for (int idx = tid; idx < 192 * 64; idx += 256) {
            int kk = idx >> 6, rem = idx & 63;
            int r = rem >> 5, j = rem & 31;
            float2 v = *(const float2*)&xb[(size_t)kk * (HF * WF) + (size_t)r * WF + 2 * j];
            *(__half2*)&Bs[kk * BS_PAD + 4 * j + 2 * r] = __floats2half2_rn(v.x, v.y);
        }
    }

    const uint32_t aRowBase = sbase + K1_AOFF
        + (uint32_t)(warpM * 32 + (lane & 15)) * A_PITCH_B + ((lane >> 4) << 4);
    const uint32_t bRow = sbase
        + (uint32_t)((lane & 7) + (((lane >> 3) & 1) << 3)) * (BS_PAD * 2)
        + (uint32_t)warpN * 64;

    for (int mt9 = 0; mt9 < 9; mt9++) {
        const int co0 = mt9 * 64;
        // prefetch next A tile into other buffer
        if (mt9 < 8) {
            const uint32_t dstN = sbase + K1_AOFF + ((mt9 + 1) & 1) * A_TILE_B;
            const __half* srcN = g_wh + (size_t)(co0 + 64) * DIM;
            for (int idx = tid; idx < 1536; idx += 256) {
                int co = idx / 24, kg = idx % 24;
                cp16(dstN + co * A_PITCH_B + kg * 16, srcN + (size_t)co * DIM + kg * 8);
            }
            CP_COMMIT();
            CP_WAIT(1);
        } else {
            CP_WAIT(0);
        }
        __syncthreads();

        float acc[2][4][4];
#pragma unroll
        for (int i0 = 0; i0 < 2; i0++)
#pragma unroll
            for (int i1 = 0; i1 < 4; i1++)
#pragma unroll
                for (int i2 = 0; i2 < 4; i2++) acc[i0][i1][i2] = 0.f;

        const uint32_t aRow = aRowBase + (mt9 & 1) * A_TILE_B;
#pragma unroll
        for (int ks = 0; ks < 12; ks++) {
            uint32_t afr[2][4], bfr[4][2];
            ldsm4(afr[0], aRow + ks * 32);
            ldsm4(afr[1], aRow + 16 * A_PITCH_B + ks * 32);
#pragma unroll
            for (int nt = 0; nt < 4; nt++)
                ldsm2t(bfr[nt], bRow + (uint32_t)ks * (16 * BS_PAD * 2) + nt * 16);
#pragma unroll
            for (int mt = 0; mt < 2; mt++)
#pragma unroll
                for (int nt = 0; nt < 4; nt++)
                    mma_f16(acc[mt][nt], afr[mt], bfr[nt]);
        }

        // epilogue: 2x2 pool -> stage -> store
#pragma unroll
        for (int mt = 0; mt < 2; mt++)
#pragma unroll
            for (int nt = 0; nt < 4; nt++) {
                float m01 = fmaxf(acc[mt][nt][0], acc[mt][nt][1]);
                float m23 = fmaxf(acc[mt][nt][2], acc[mt][nt][3]);
                m01 = fmaxf(m01, __shfl_xor_sync(0xffffffffu, m01, 1));
                m23 = fmaxf(m23, __shfl_xor_sync(0xffffffffu, m23, 1));
                if (!(t4 & 1)) {
                    int pj = warpN * 8 + nt * 2 + (t4 >> 1);
                    int co = warpM * 32 + mt * 16 + g;
                    ps[co * 36 + pj] = m01;
                    ps[(co + 8) * 36 + pj] = m23;
                }
            }
        __syncthreads();
        for (int idx = tid; idx < 64 * 8; idx += 256) {
            int row = idx >> 3, c4 = idx & 7;
            float4 v = *(const float4*)&ps[row * 36 + c4 * 4];
            *(float4*)&g_P[(((size_t)b * C3 + co0 + row) * HP + pi) * WP + pj0 + c4 * 4] = v;
        }
        __syncthreads();
    }
}

// ---------------------------------------------------------------------------
// K7: proj 1x1 conv at LOW-res fp16 MMA (cp.async double-buffered A) +
// nearest-x2 duplicate DIRECT stores (no staging smem).
// smem: Bs 52224 | As 2x25600 = 103424B.
// ---------------------------------------------------------------------------
#define K7_AOFF 52224
#define K7_SMEM (52224 + 2 * A_TILE_B)

__global__ void __launch_bounds__(256, 2) k7_mma(float* __restrict__ out) {
    extern __shared__ __align__(16) char smem[];
    __half* Bs = (__half*)smem;
    uint32_t sbase;
    asm("{ .reg .u64 t; cvta.to.shared.u64 t, %1; cvt.u32.u64 %0, t; }"
        : "=r"(sbase) : "l"(smem));

    const int tid = threadIdx.x;
    const int ctaN = blockIdx.x, b = blockIdx.z;   // low-res row
    const int lane = tid & 31, warp = tid >> 5;
    const int warpM = warp >> 2, warpN = warp & 3;
    const int g = lane >> 2, t4 = lane & 3;

    // prefetch A tile 0
    {
        const uint32_t dst0 = sbase + K7_AOFF;
        for (int idx = tid; idx < 1536; idx += 256) {
            int co = idx / 24, kg = idx % 24;
            cp16(dst0 + co * A_PITCH_B + kg * 16, &g_pwh[(size_t)co * DIM + kg * 8]);
        }
        CP_COMMIT();
    }

    // resident B: one low-res row, 192k x 128px fp16 passthrough
    {
        const __half* xb = g_low + (size_t)b * DIM * NPX + (size_t)ctaN * 128;
        for (int idx = tid; idx < 192 * 16; idx += 256) {
            int kk = idx >> 4, jg = idx & 15;
            *(uint4*)&Bs[kk * BS_PAD + jg * 8] =
                *(const uint4*)&xb[(size_t)kk * NPX + jg * 8];
        }
    }

    const uint32_t aRowBase = sbase + K7_AOFF
        + (uint32_t)(warpM * 32 + (lane & 15)) * A_PITCH_B + ((lane >> 4) << 4);
    const uint32_t bRow = sbase
        + (uint32_t)((lane & 7) + (((lane >> 3) & 1) << 3)) * (BS_PAD * 2)
        + (uint32_t)warpN * 64;

    for (int mt3 = 0; mt3 < 3; mt3++) {
        const int co0 = mt3 * 64;
        if (mt3 < 2) {
            const uint32_t dstN = sbase + K7_AOFF + ((mt3 + 1) & 1) * A_TILE_B;
            const __half* srcN = g_pwh + (size_t)(co0 + 64) * DIM;
            for (int idx = tid; idx < 1536; idx += 256) {
                int co = idx / 24, kg = idx % 24;
                cp16(dstN + co * A_PITCH_B + kg * 16, srcN + (size_t)co * DIM + kg * 8);
            }
            CP_COMMIT();
            CP_WAIT(1);
        } else {
            CP_WAIT(0);
        }
        __syncthreads();

        float acc[2][4][4];
#pragma unroll
        for (int i0 = 0; i0 < 2; i0++)
#pragma unroll
            for (int i1 = 0; i1 < 4; i1++)
#pragma unroll
                for (int i2 = 0; i2 < 4; i2++) acc[i0][i1][i2] = 0.f;

        const uint32_t aRow = aRowBase + (mt3 & 1) * A_TILE_B;
#pragma unroll
        for (int ks = 0; ks < 12; ks++) {
            uint32_t afr[2][4], bfr[4][2];
            ldsm4(afr[0], aRow + ks * 32);
            ldsm4(afr[1], aRow + 16 * A_PITCH_B + ks * 32);
#pragma unroll
            for (int nt = 0; nt < 4; nt++)
                ldsm2t(bfr[nt], bRow + (uint32_t)ks * (16 * BS_PAD * 2) + nt * 16);
#pragma unroll
            for (int mt = 0; mt < 2; mt++)
#pragma unroll
                for (int nt = 0; nt < 4; nt++)
                    mma_f16(acc[mt][nt], afr[mt], bfr[nt]);
        }

        // direct duplicate-store epilogue (no smem staging)
#pragma unroll
        for (int mt = 0; mt < 2; mt++) {
            const int coA0 = co0 + warpM * 32 + mt * 16 + g;
#pragma unroll
            for (int nt = 0; nt < 4; nt++) {
                const int n = warpN * 32 + nt * 8 + 2 * t4;      // low-res col
                {
                    float4 v = make_float4(acc[mt][nt][0], acc[mt][nt][0],
                                           acc[mt][nt][1], acc[mt][nt][1]);
                    float* ob = out + (size_t)(b * DIM + coA0) * (HF * WF)
                                    + (size_t)(2 * ctaN) * WF + 2 * n;
                    *(float4*)ob = v;
                    *(float4*)(ob + WF) = v;
                }
                {
                    float4 v = make_float4(acc[mt][nt][2], acc[mt][nt][2],
                                           acc[mt][nt][3], acc[mt][nt][3]);
                    float* ob = out + (size_t)(b * DIM + coA0 + 8) * (HF * WF)
                                    + (size_t)(2 * ctaN) * WF + 2 * n;
                    *(float4*)ob = v;
                    *(float4*)(ob + WF) = v;
                }
            }
        }
        __syncthreads();
    }
}

// ---------------------------------------------------------------------------
// K2: depthwise 3x3 SAME (32 rows/block) + fp16 q/k side-write + fused norms.
// ---------------------------------------------------------------------------
__global__ void __launch_bounds__(256) k2_dw(const float* __restrict__ dw) {
    int strip = blockIdx.x, c = blockIdx.y, b = blockIdx.z;
    int i0 = strip * 32;
    int tid = threadIdx.x;
    int lane = tid & 31, warp = tid >> 5;
    __shared__ float s[34][132];
    __shared__ float red[8];
    const float* base = g_P + (size_t)(b * C3 + c) * HP * WP;
    for (int idx = tid; idx < 34 * 32; idx += 256) {
        int r = idx >> 5, c4 = idx & 31;
        int ri = i0 - 1 + r;
        float4 v = make_float4(0.f, 0.f, 0.f, 0.f);
        if (ri >= 0 && ri < HP) v = *(const float4*)&base[(size_t)ri * WP + c4 * 4];
        s[r][1 + c4 * 4 + 0] = v.x; s[r][1 + c4 * 4 + 1] = v.y;
        s[r][1 + c4 * 4 + 2] = v.z; s[r][1 + c4 * 4 + 3] = v.w;
    }
    if (tid < 34) { s[tid][0] = 0.f; s[tid][129] = 0.f; }
    __syncthreads();

    float k00 = dw[c * 9 + 0], k01 = dw[c * 9 + 1], k02 = dw[c * 9 + 2];
    float k10 = dw[c * 9 + 3], k11 = dw[c * 9 + 4], k12 = dw[c * 9 + 5];
    float k20 = dw[c * 9 + 6], k21 = dw[c * 9 + 7], k22 = dw[c * 9 + 8];

    int j = tid & 127;
    int r0 = (tid >> 7) * 16;
    const bool isqk = (c < 384);
    float a0 = s[r0][j],     a1 = s[r0][j + 1],     a2 = s[r0][j + 2];
    float b0 = s[r0 + 1][j], b1 = s[r0 + 1][j + 1], b2 = s[r0 + 1][j + 2];
    float*  ob  = g_D + ((size_t)(b * C3 + c) * HP + i0 + r0) * WP + j;
    __half* obh = g_Dh + ((size_t)(b * 384 + (isqk ? c : 0)) * HP + i0 + r0) * WP + j;
    float nrm = 0.f;
#pragma unroll
    for (int r = 0; r < 16; r++) {
        float c0 = s[r0 + r + 2][j], c1 = s[r0 + r + 2][j + 1], c2 = s[r0 + r + 2][j + 2];
        float acc = k00 * a0;
        acc = fmaf(k01, a1, acc); acc = fmaf(k02, a2, acc);
        acc = fmaf(k10, b0, acc); acc = fmaf(k11, b1, acc); acc = fmaf(k12, b2, acc);
        acc = fmaf(k20, c0, acc); acc = fmaf(k21, c1, acc); acc = fmaf(k22, c2, acc);
        ob[(size_t)r * WP] = acc;
        if (isqk) {
            __half hv = __float2half_rn(acc);
            obh[(size_t)r * WP] = hv;
            float hf = __half2float(hv);
            nrm = fmaf(hf, hf, nrm);
        }
        a0 = b0; a1 = b1; a2 = b2;
        b0 = c0; b1 = c1; b2 = c2;
    }
#pragma unroll
    for (int o = 16; o; o >>= 1) nrm += __shfl_xor_sync(0xffffffffu, nrm, o);
    if (lane == 0) red[warp] = nrm;
    __syncthreads();
    if (tid == 0 && isqk) {
        float t = red[0] + red[1] + red[2] + red[3] + red[4] + red[5] + red[6] + red[7];
        float* dst = (c < 192)
            ? &g_sq[(b * NHEADS + (c >> 5)) * CPH + (c & 31)]
            : &g_sk[(b * NHEADS + ((c - 192) >> 5)) * CPH + ((c - 192) & 31)];
        atomicAdd(dst, t);
    }
}

__global__ void k_init() {
    int idx = blockIdx.x * blockDim.x + threadIdx.x;
    if (idx < BB * NHEADS * CPH * CPH) g_G[idx] = 0.f;
    if (idx < BB * NHEADS * CPH) { g_sq[idx] = 0.f; g_sk[idx] = 0.f; }
}

// ---------------------------------------------------------------------------
// K4: gram via fp16 MMA, fragments loaded DIRECTLY from global.
// ---------------------------------------------------------------------------
__global__ void __launch_bounds__(256) k4_mma() {
    const int split = blockIdx.x, bh = blockIdx.y;
    const int b = bh / NHEADS, h = bh % NHEADS;
    const int tid = threadIdx.x;
    const int lane = tid & 31, warp = tid >> 5;
    const int g = lane >> 2, cpair = (lane & 3) * 2;

    __shared__ float Gs[32][33];
    for (int idx = tid; idx < 32 * 33; idx += 256) (&Gs[0][0])[idx] = 0.f;
    __syncthreads();

    const __half* qb = g_Dh + (size_t)(b * 384 + h * CPH) * NPX;
    const __half* kb = g_Dh + (size_t)(b * 384 + 192 + h * CPH) * NPX;

    float acc[2][4][4];
#pragma unroll
    for (int i0 = 0; i0 < 2; i0++)
#pragma unroll
        for (int i1 = 0; i1 < 4; i1++)
#pragma unroll
            for (int i2 = 0; i2 < 4; i2++) acc[i0][i1][i2] = 0.f;

    const int n_base = (split * 8 + warp) * 64;
#pragma unroll
    for (int kt = 0; kt < 4; kt++) {
        const int n0 = n_base + kt * 16;
        uint32_t a[2][4], bb[4][2];
#pragma unroll
        for (int mt = 0; mt < 2; mt++) {
            const __half* qrow = qb + (size_t)(mt * 16 + g) * NPX + n0 + cpair;
            a[mt][0] = *(const uint32_t*)(qrow);
            a[mt][1] = *(const uint32_t*)(qrow + 8 * NPX);
            a[mt][2] = *(const uint32_t*)(qrow + 8);
            a[mt][3] = *(const uint32_t*)(qrow + 8 * NPX + 8);
        }
#pragma unroll
        for (int nt = 0; nt < 4; nt++) {
            const __half* krow = kb + (size_t)(nt * 8 + g) * NPX + n0 + cpair;
            bb[nt][0] = *(const uint32_t*)(krow);
            bb[nt][1] = *(const uint32_t*)(krow + 8);
        }
#pragma unroll
        for (int mt = 0; mt < 2; mt++)
#pragma unroll
            for (int nt = 0; nt < 4; nt++)
                mma_f16(acc[mt][nt], a[mt], bb[nt]);
    }
#pragma unroll
    for (int mt = 0; mt < 2; mt++)
#pragma unroll
        for (int nt = 0; nt < 4; nt++) {
            atomicAdd(&Gs[mt * 16 + g][nt * 8 + cpair],         acc[mt][nt][0]);
            atomicAdd(&Gs[mt * 16 + g][nt * 8 + cpair + 1],     acc[mt][nt][1]);
            atomicAdd(&Gs[mt * 16 + g + 8][nt * 8 + cpair],     acc[mt][nt][2]);
            atomicAdd(&Gs[mt * 16 + g + 8][nt * 8 + cpair + 1], acc[mt][nt][3]);
        }
    __syncthreads();
    for (int idx = tid; idx < 1024; idx += 256)
        atomicAdd(&g_G[(size_t)bh * 1024 + idx], Gs[idx >> 5][idx & 31]);
}

// ---------------------------------------------------------------------------
// K5: normalize gram -> attn, 4 top-k masked softmaxes fused into combined A.
// ---------------------------------------------------------------------------
__global__ void k5_softmax(const float* __restrict__ temp,
                           const float* __restrict__ a1p, const float* __restrict__ a2p,
                           const float* __restrict__ a3p, const float* __restrict__ a4p) {
    int bh = blockIdx.x;
    int h = bh % NHEADS;
    int tid = threadIdx.x;
    int warp = tid >> 5, d = tid & 31;
    float t = temp[h];
    float A1 = *a1p, A2 = *a2p, A3 = *a3p, A4 = *a4p;
    float rk = 1.f / fmaxf(sqrtf(g_sk[bh * CPH + d]), 1e-12f);
    for (int it = 0; it < 4; it++) {
        int c = warp * 4 + it;
        float rq = 1.f / fmaxf(sqrtf(g_sq[bh * CPH + c]), 1e-12f);
        float v = g_G[((size_t)bh * CPH + c) * CPH + d] * rq * rk * t;
        int rank = 0;
#pragma unroll
        for (int j = 0; j < 32; j++) {
            float vj = __shfl_sync(0xffffffffu, v, j);
            rank += (vj > v) || (vj == v && j < d);
        }
        float vmax = v;
#pragma unroll
        for (int o = 16; o; o >>= 1) vmax = fmaxf(vmax, __shfl_xor_sync(0xffffffffu, vmax, o));
        float e = expf(v - vmax);
        float e1 = rank < 16 ? e : 0.f;
        float e2 = rank < 21 ? e : 0.f;
        float e3 = rank < 24 ? e : 0.f;
        float e4 = rank < 25 ? e : 0.f;
#pragma unroll
        for (int o = 16; o; o >>= 1) {
            e1 += __shfl_xor_sync(0xffffffffu, e1, o);
            e2 += __shfl_xor_sync(0xffffffffu, e2, o);
            e3 += __shfl_xor_sync(0xffffffffu, e3, o);
            e4 += __shfl_xor_sync(0xffffffffu, e4, o);
        }
        float wgt = (rank < 16 ? A1 / e1 : 0.f) + (rank < 21 ? A2 / e2 : 0.f)
                  + (rank < 24 ? A3 / e3 : 0.f) + (rank < 25 ? A4 / e4 : 0.f);
        g_A[((size_t)bh * CPH + c) * CPH + d] = e * wgt;
    }
}

// ---------------------------------------------------------------------------
// K6: out_low = A @ v (fp32 exact), GELU, store fp16 g_low.
// ---------------------------------------------------------------------------
__global__ void __launch_bounds__(256) k6_apply() {
    int bh = blockIdx.y;
    int b = bh / NHEADS, h = bh % NHEADS;
    int tid = threadIdx.x;
    __shared__ float As[32][32];
    reinterpret_cast<float4*>(&As[0][0])[tid] =
        reinterpret_cast<const float4*>(&g_A[(size_t)bh * 1024])[tid];
    __syncthreads();
    int px = blockIdx.x * 256 + tid;
    const float* vb = g_D + (size_t)(b * C3 + 2 * DIM + h * CPH) * NPX + px;
    float acc[32];
#pragma unroll
    for (int c = 0; c < 32; c++) acc[c] = 0.f;
#pragma unroll 4
    for (int d = 0; d < 32; d++) {
        float vd = vb[(size_t)d * NPX];
#pragma unroll
        for (int c = 0; c < 32; c++) acc[c] = fmaf(As[c][d], vd, acc[c]);
    }
    __half* ob = g_low + (size_t)(b * DIM + h * CPH) * NPX + px;
#pragma unroll
    for (int c = 0; c < 32; c++) {
        float xg = acc[c];
        ob[(size_t)c * NPX] =
            __float2half_rn(0.5f * xg * (1.f + erff(xg * 0.70710678118654752f)));
    }
}

extern "C" void kernel_launch(void* const* d_in, const int* in_sizes, int n_in,
                              void* d_out, int out_size) {
    const float* x      = (const float*)d_in[0];
    const float* temp   = (const float*)d_in[1];
    const float* qkv_w  = (const float*)d_in[2];
    const float* dw_w   = (const float*)d_in[3];
    const float* proj_w = (const float*)d_in[4];
    const float* a1     = (const float*)d_in[5];
    const float* a2     = (const float*)d_in[6];
    const float* a3     = (const float*)d_in[7];
    const float* a4     = (const float*)d_in[8];
    float* out = (float*)d_out;

    cudaFuncSetAttribute(k1_mma, cudaFuncAttributeMaxDynamicSharedMemorySize, K1_SMEM);
    cudaFuncSetAttribute(k7_mma, cudaFuncAttributeMaxDynamicSharedMemorySize, K7_SMEM);

    k_init<<<96, 256>>>();
    k0_convert<<<144, 256>>>(qkv_w, proj_w);
    k1_mma<<<dim3(512, 1, 4), 256, K1_SMEM>>>(x);
    k2_dw<<<dim3(4, 576, 4), 256>>>(dw_w);
    k4_mma<<<dim3(32, 24), 256>>>();
    k5_softmax<<<24, 256>>>(temp, a1, a2, a3, a4);
    k6_apply<<<dim3(64, 24), 256>>>();
    k7_mma<<<dim3(128, 1, 4), 256, K7_SMEM>>>(out);
}

// round 15
// speedup vs baseline: 1.7373x; 1.3500x over previous
#include <cuda_runtime.h>
#include <cuda_fp16.h>
#include <math.h>
#include <stdint.h>

#define BB 4
#define DIM 192
#define C3 576
#define HF 256
#define WF 256
#define HP 128
#define WP 128
#define NPX 16384
#define NHEADS 6
#define CPH 32

// scratch (device globals: allocation-free)
__device__ __half g_Ph[BB * C3 * HP * WP];     // pooled qkv, fp16
__device__ __half g_Dh[BB * C3 * HP * WP];     // after dwconv, q|k|v fp16
__device__ __half g_low[BB * DIM * NPX];       // gelu(out) low-res, fp16
__device__ __half g_wh[C3 * DIM];              // qkv_w fp16
__device__ __half g_pwh[DIM * DIM];            // proj_w fp16
__device__ float  g_G[BB * NHEADS * CPH * CPH];
__device__ __half g_Ah[BB * NHEADS * CPH * CPH];
__device__ float  g_sq[BB * NHEADS * CPH];
__device__ float  g_sk[BB * NHEADS * CPH];

// ============================ MMA / async helpers ==========================
__device__ __forceinline__ void mma_f16(float* d, const uint32_t* a, const uint32_t* b) {
    asm volatile(
        "mma.sync.aligned.m16n8k16.row.col.f32.f16.f16.f32 "
        "{%0,%1,%2,%3}, {%4,%5,%6,%7}, {%8,%9}, {%0,%1,%2,%3};"
        : "+f"(d[0]), "+f"(d[1]), "+f"(d[2]), "+f"(d[3])
        : "r"(a[0]), "r"(a[1]), "r"(a[2]), "r"(a[3]), "r"(b[0]), "r"(b[1]));
}
__device__ __forceinline__ void ldsm4(uint32_t* r, uint32_t a) {
    asm volatile("ldmatrix.sync.aligned.m8n8.x4.shared.b16 {%0,%1,%2,%3}, [%4];"
        : "=r"(r[0]), "=r"(r[1]), "=r"(r[2]), "=r"(r[3]) : "r"(a));
}
__device__ __forceinline__ void ldsm2t(uint32_t* r, uint32_t a) {
    asm volatile("ldmatrix.sync.aligned.m8n8.x2.trans.shared.b16 {%0,%1}, [%2];"
        : "=r"(r[0]), "=r"(r[1]) : "r"(a));
}
__device__ __forceinline__ uint32_t h2u(__half2 h) { return *(uint32_t*)&h; }
__device__ __forceinline__ void cp16(uint32_t dst, const void* src) {
    asm volatile("cp.async.cg.shared.global [%0], [%1], 16;" :: "r"(dst), "l"(src));
}
#define CP_COMMIT() asm volatile("cp.async.commit_group;" ::: "memory")
#define CP_WAIT(n)  asm volatile("cp.async.wait_group %0;" :: "n"(n) : "memory")

#define BS_PAD 136      // fp16 per B row (272B)
#define A_PITCH_B 400   // bytes per A row (192 fp16 = 384B + 16 pad)
#define A_TILE_B 25600  // 64 rows * 400B

// ---------------------------------------------------------------------------
// K0: convert weights fp32 -> fp16 once.
// ---------------------------------------------------------------------------
__global__ void k0_convert(const float* __restrict__ qkv_w,
                           const float* __restrict__ proj_w) {
    int i = blockIdx.x * blockDim.x + threadIdx.x;
    const int n1 = C3 * DIM / 4;
    const int n2 = DIM * DIM / 4;
    if (i < n1) {
        float4 f = *(const float4*)&qkv_w[i * 4];
        *(uint2*)&g_wh[i * 4] = make_uint2(h2u(__floats2half2_rn(f.x, f.y)),
                                           h2u(__floats2half2_rn(f.z, f.w)));
    } else if (i < n1 + n2) {
        int j = i - n1;
        float4 f = *(const float4*)&proj_w[j * 4];
        *(uint2*)&g_pwh[j * 4] = make_uint2(h2u(__floats2half2_rn(f.x, f.y)),
                                            h2u(__floats2half2_rn(f.z, f.w)));
    }
}

// ---------------------------------------------------------------------------
// K1: qkv 1x1 conv fp16 MMA + fused 2x2 maxpool -> fp16 g_Ph.
// B resident, A tiles cp.async double-buffered.
// smem: Bs 52224 | As 2x25600 | ps 64x40 half (5120B) = 108544B.
// ---------------------------------------------------------------------------
#define K1_AOFF 52224
#define K1_POFF (52224 + 2 * A_TILE_B)
#define K1_SMEM (K1_POFF + 5120)

__global__ void __launch_bounds__(256, 2) k1_mma(const float* __restrict__ x) {
    extern __shared__ __align__(16) char smem[];
    __half* Bs = (__half*)smem;
    __half* ps = (__half*)(smem + K1_POFF);
    uint32_t sbase;
    asm("{ .reg .u64 t; cvta.to.shared.u64 t, %1; cvt.u32.u64 %0, t; }"
        : "=r"(sbase) : "l"(smem));

    const int tid = threadIdx.x;
    const int ctaN = blockIdx.x, b = blockIdx.z;
    const int lane = tid & 31, warp = tid >> 5;
    const int warpM = warp >> 2, warpN = warp & 3;
    const int g = lane >> 2, t4 = lane & 3;

    const int pi = ctaN >> 2;
    const int pj0 = (ctaN & 3) * 32;

    // prefetch A tile 0
    {
        const uint32_t dst0 = sbase + K1_AOFF;
        for (int idx = tid; idx < 1536; idx += 256) {
            int co = idx / 24, kg = idx % 24;
            cp16(dst0 + co * A_PITCH_B + kg * 16, &g_wh[(size_t)co * DIM + kg * 8]);
        }
        CP_COMMIT();
    }

    // resident B: n = 4*j + 2*r + e (pooled-quad interleave), fp16
    {
        const float* xb = x + (size_t)b * DIM * (HF * WF)
                            + (size_t)(2 * pi) * WF + 2 * pj0;
        for (int idx = tid; idx < 192 * 64; idx += 256) {
            int kk = idx >> 6, rem = idx & 63;
            int r = rem >> 5, j = rem & 31;
            float2 v = *(const float2*)&xb[(size_t)kk * (HF * WF) + (size_t)r * WF + 2 * j];
            *(__half2*)&Bs[kk * BS_PAD + 4 * j + 2 * r] = __floats2half2_rn(v.x, v.y);
        }
    }

    const uint32_t aRowBase = sbase + K1_AOFF
        + (uint32_t)(warpM * 32 + (lane & 15)) * A_PITCH_B + ((lane >> 4) << 4);
    const uint32_t bRow = sbase
        + (uint32_t)((lane & 7) + (((lane >> 3) & 1) << 3)) * (BS_PAD * 2)
        + (uint32_t)warpN * 64;

    for (int mt9 = 0; mt9 < 9; mt9++) {
        const int co0 = mt9 * 64;
        if (mt9 < 8) {
            const uint32_t dstN = sbase + K1_AOFF + ((mt9 + 1) & 1) * A_TILE_B;
            const __half* srcN = g_wh + (size_t)(co0 + 64) * DIM;
            for (int idx = tid; idx < 1536; idx += 256) {
                int co = idx / 24, kg = idx % 24;
                cp16(dstN + co * A_PITCH_B + kg * 16, srcN + (size_t)co * DIM + kg * 8);
            }
            CP_COMMIT();
            CP_WAIT(1);
        } else {
            CP_WAIT(0);
        }
        __syncthreads();

        float acc[2][4][4];
#pragma unroll
        for (int i0 = 0; i0 < 2; i0++)
#pragma unroll
            for (int i1 = 0; i1 < 4; i1++)
#pragma unroll
                for (int i2 = 0; i2 < 4; i2++) acc[i0][i1][i2] = 0.f;

        const uint32_t aRow = aRowBase + (mt9 & 1) * A_TILE_B;
#pragma unroll
        for (int ks = 0; ks < 12; ks++) {
            uint32_t afr[2][4], bfr[4][2];
            ldsm4(afr[0], aRow + ks * 32);
            ldsm4(afr[1], aRow + 16 * A_PITCH_B + ks * 32);
#pragma unroll
            for (int nt = 0; nt < 4; nt++)
                ldsm2t(bfr[nt], bRow + (uint32_t)ks * (16 * BS_PAD * 2) + nt * 16);
#pragma unroll
            for (int mt = 0; mt < 2; mt++)
#pragma unroll
                for (int nt = 0; nt < 4; nt++)
                    mma_f16(acc[mt][nt], afr[mt], bfr[nt]);
        }

        // epilogue: 2x2 pool -> fp16 stage -> store
#pragma unroll
        for (int mt = 0; mt < 2; mt++)
#pragma unroll
            for (int nt = 0; nt < 4; nt++) {
                float m01 = fmaxf(acc[mt][nt][0], acc[mt][nt][1]);
                float m23 = fmaxf(acc[mt][nt][2], acc[mt][nt][3]);
                m01 = fmaxf(m01, __shfl_xor_sync(0xffffffffu, m01, 1));
                m23 = fmaxf(m23, __shfl_xor_sync(0xffffffffu, m23, 1));
                if (!(t4 & 1)) {
                    int pj = warpN * 8 + nt * 2 + (t4 >> 1);
                    int co = warpM * 32 + mt * 16 + g;
                    ps[co * 40 + pj] = __float2half_rn(m01);
                    ps[(co + 8) * 40 + pj] = __float2half_rn(m23);
                }
            }
        __syncthreads();
        for (int idx = tid; idx < 64 * 4; idx += 256) {
            int row = idx >> 2, c8 = idx & 3;
            uint4 v = *(const uint4*)&ps[row * 40 + c8 * 8];
            *(uint4*)&g_Ph[(((size_t)b * C3 + co0 + row) * HP + pi) * WP + pj0 + c8 * 8] = v;
        }
        __syncthreads();
    }
}

// ---------------------------------------------------------------------------
// K7: proj 1x1 conv at LOW-res fp16 MMA + nearest-x2 duplicate direct stores.
// ---------------------------------------------------------------------------
#define K7_AOFF 52224
#define K7_SMEM (52224 + 2 * A_TILE_B)

__global__ void __launch_bounds__(256, 2) k7_mma(float* __restrict__ out) {
    extern __shared__ __align__(16) char smem[];
    __half* Bs = (__half*)smem;
    uint32_t sbase;
    asm("{ .reg .u64 t; cvta.to.shared.u64 t, %1; cvt.u32.u64 %0, t; }"
        : "=r"(sbase) : "l"(smem));

    const int tid = threadIdx.x;
    const int ctaN = blockIdx.x, b = blockIdx.z;
    const int lane = tid & 31, warp = tid >> 5;
    const int warpM = warp >> 2, warpN = warp & 3;
    const int g = lane >> 2, t4 = lane & 3;

    {
        const uint32_t dst0 = sbase + K7_AOFF;
        for (int idx = tid; idx < 1536; idx += 256) {
            int co = idx / 24, kg = idx % 24;
            cp16(dst0 + co * A_PITCH_B + kg * 16, &g_pwh[(size_t)co * DIM + kg * 8]);
        }
        CP_COMMIT();
    }
    {
        const __half* xb = g_low + (size_t)b * DIM * NPX + (size_t)ctaN * 128;
        for (int idx = tid; idx < 192 * 16; idx += 256) {
            int kk = idx >> 4, jg = idx & 15;
            *(uint4*)&Bs[kk * BS_PAD + jg * 8] =
                *(const uint4*)&xb[(size_t)kk * NPX + jg * 8];
        }
    }

    const uint32_t aRowBase = sbase + K7_AOFF
        + (uint32_t)(warpM * 32 + (lane & 15)) * A_PITCH_B + ((lane >> 4) << 4);
    const uint32_t bRow = sbase
        + (uint32_t)((lane & 7) + (((lane >> 3) & 1) << 3)) * (BS_PAD * 2)
        + (uint32_t)warpN * 64;

    for (int mt3 = 0; mt3 < 3; mt3++) {
        const int co0 = mt3 * 64;
        if (mt3 < 2) {
            const uint32_t dstN = sbase + K7_AOFF + ((mt3 + 1) & 1) * A_TILE_B;
            const __half* srcN = g_pwh + (size_t)(co0 + 64) * DIM;
            for (int idx = tid; idx < 1536; idx += 256) {
                int co = idx / 24, kg = idx % 24;
                cp16(dstN + co * A_PITCH_B + kg * 16, srcN + (size_t)co * DIM + kg * 8);
            }
            CP_COMMIT();
            CP_WAIT(1);
        } else {
            CP_WAIT(0);
        }
        __syncthreads();

        float acc[2][4][4];
#pragma unroll
        for (int i0 = 0; i0 < 2; i0++)
#pragma unroll
            for (int i1 = 0; i1 < 4; i1++)
#pragma unroll
                for (int i2 = 0; i2 < 4; i2++) acc[i0][i1][i2] = 0.f;

        const uint32_t aRow = aRowBase + (mt3 & 1) * A_TILE_B;
#pragma unroll
        for (int ks = 0; ks < 12; ks++) {
            uint32_t afr[2][4], bfr[4][2];
            ldsm4(afr[0], aRow + ks * 32);
            ldsm4(afr[1], aRow + 16 * A_PITCH_B + ks * 32);
#pragma unroll
            for (int nt = 0; nt < 4; nt++)
                ldsm2t(bfr[nt], bRow + (uint32_t)ks * (16 * BS_PAD * 2) + nt * 16);
#pragma unroll
            for (int mt = 0; mt < 2; mt++)
#pragma unroll
                for (int nt = 0; nt < 4; nt++)
                    mma_f16(acc[mt][nt], afr[mt], bfr[nt]);
        }

#pragma unroll
        for (int mt = 0; mt < 2; mt++) {
            const int coA0 = co0 + warpM * 32 + mt * 16 + g;
#pragma unroll
            for (int nt = 0; nt < 4; nt++) {
                const int n = warpN * 32 + nt * 8 + 2 * t4;
                {
                    float4 v = make_float4(acc[mt][nt][0], acc[mt][nt][0],
                                           acc[mt][nt][1], acc[mt][nt][1]);
                    float* ob = out + (size_t)(b * DIM + coA0) * (HF * WF)
                                    + (size_t)(2 * ctaN) * WF + 2 * n;
                    *(float4*)ob = v;
                    *(float4*)(ob + WF) = v;
                }
                {
                    float4 v = make_float4(acc[mt][nt][2], acc[mt][nt][2],
                                           acc[mt][nt][3], acc[mt][nt][3]);
                    float* ob = out + (size_t)(b * DIM + coA0 + 8) * (HF * WF)
                                    + (size_t)(2 * ctaN) * WF + 2 * n;
                    *(float4*)ob = v;
                    *(float4*)(ob + WF) = v;
                }
            }
        }
        __syncthreads();
    }
}

// ---------------------------------------------------------------------------
// K2: depthwise 3x3 SAME, fp16 in (g_Ph) / fp16 out (g_Dh all 576 ch) +
// fused q/k norms. fp32 internal math.
// ---------------------------------------------------------------------------
__global__ void __launch_bounds__(256) k2_dw(const float* __restrict__ dw) {
    int strip = blockIdx.x, c = blockIdx.y, b = blockIdx.z;
    int i0 = strip * 32;
    int tid = threadIdx.x;
    int lane = tid & 31, warp = tid >> 5;
    __shared__ float s[34][132];
    __shared__ float red[8];
    const __half* base = g_Ph + (size_t)(b * C3 + c) * HP * WP;
    for (int idx = tid; idx < 34 * 16; idx += 256) {
        int r = idx >> 4, c8 = idx & 15;
        int ri = i0 - 1 + r;
        if (ri >= 0 && ri < HP) {
            uint4 u = *(const uint4*)&base[(size_t)ri * WP + c8 * 8];
            __half2* hp = (__half2*)&u;
#pragma unroll
            for (int q2 = 0; q2 < 4; q2++) {
                float2 f = __half22float2(hp[q2]);
                s[r][1 + c8 * 8 + q2 * 2] = f.x;
                s[r][1 + c8 * 8 + q2 * 2 + 1] = f.y;
            }
        } else {
#pragma unroll
            for (int q2 = 0; q2 < 8; q2++) s[r][1 + c8 * 8 + q2] = 0.f;
        }
    }
    if (tid < 34) { s[tid][0] = 0.f; s[tid][129] = 0.f; }
    __syncthreads();

    float k00 = dw[c * 9 + 0], k01 = dw[c * 9 + 1], k02 = dw[c * 9 + 2];
    float k10 = dw[c * 9 + 3], k11 = dw[c * 9 + 4], k12 = dw[c * 9 + 5];
    float k20 = dw[c * 9 + 6], k21 = dw[c * 9 + 7], k22 = dw[c * 9 + 8];

    int j = tid & 127;
    int r0 = (tid >> 7) * 16;
    const bool isqk = (c < 384);
    float a0 = s[r0][j],     a1 = s[r0][j + 1],     a2 = s[r0][j + 2];
    float b0 = s[r0 + 1][j], b1 = s[r0 + 1][j + 1], b2 = s[r0 + 1][j + 2];
    __half* obh = g_Dh + ((size_t)(b * C3 + c) * HP + i0 + r0) * WP + j;
    float nrm = 0.f;
#pragma unroll
    for (int r = 0; r < 16; r++) {
        float c0 = s[r0 + r + 2][j], c1 = s[r0 + r + 2][j + 1], c2 = s[r0 + r + 2][j + 2];
        float acc = k00 * a0;
        acc = fmaf(k01, a1, acc); acc = fmaf(k02, a2, acc);
        acc = fmaf(k10, b0, acc); acc = fmaf(k11, b1, acc); acc = fmaf(k12, b2, acc);
        acc = fmaf(k20, c0, acc); acc = fmaf(k21, c1, acc); acc = fmaf(k22, c2, acc);
        __half hv = __float2half_rn(acc);
        obh[(size_t)r * WP] = hv;
        if (isqk) {
            float hf = __half2float(hv);
            nrm = fmaf(hf, hf, nrm);
        }
        a0 = b0; a1 = b1; a2 = b2;
        b0 = c0; b1 = c1; b2 = c2;
    }
#pragma unroll
    for (int o = 16; o; o >>= 1) nrm += __shfl_xor_sync(0xffffffffu, nrm, o);
    if (lane == 0) red[warp] = nrm;
    __syncthreads();
    if (tid == 0 && isqk) {
        float t = red[0] + red[1] + red[2] + red[3] + red[4] + red[5] + red[6] + red[7];
        float* dst = (c < 192)
            ? &g_sq[(b * NHEADS + (c >> 5)) * CPH + (c & 31)]
            : &g_sk[(b * NHEADS + ((c - 192) >> 5)) * CPH + ((c - 192) & 31)];
        atomicAdd(dst, t);
    }
}

__global__ void k_init() {
    int idx = blockIdx.x * blockDim.x + threadIdx.x;
    if (idx < BB * NHEADS * CPH * CPH) g_G[idx] = 0.f;
    if (idx < BB * NHEADS * CPH) { g_sq[idx] = 0.f; g_sk[idx] = 0.f; }
}

// ---------------------------------------------------------------------------
// K4: gram via fp16 MMA, fragments loaded directly from global.
// ---------------------------------------------------------------------------
__global__ void __launch_bounds__(256) k4_mma() {
    const int split = blockIdx.x, bh = blockIdx.y;
    const int b = bh / NHEADS, h = bh % NHEADS;
    const int tid = threadIdx.x;
    const int lane = tid & 31, warp = tid >> 5;
    const int g = lane >> 2, cpair = (lane & 3) * 2;

    __shared__ float Gs[32][33];
    for (int idx = tid; idx < 32 * 33; idx += 256) (&Gs[0][0])[idx] = 0.f;
    __syncthreads();

    const __half* qb = g_Dh + (size_t)(b * C3 + h * CPH) * NPX;
    const __half* kb = g_Dh + (size_t)(b * C3 + 192 + h * CPH) * NPX;

    float acc[2][4][4];
#pragma unroll
    for (int i0 = 0; i0 < 2; i0++)
#pragma unroll
        for (int i1 = 0; i1 < 4; i1++)
#pragma unroll
            for (int i2 = 0; i2 < 4; i2++) acc[i0][i1][i2] = 0.f;

    const int n_base = (split * 8 + warp) * 64;
#pragma unroll
    for (int kt = 0; kt < 4; kt++) {
        const int n0 = n_base + kt * 16;
        uint32_t a[2][4], bb[4][2];
#pragma unroll
        for (int mt = 0; mt < 2; mt++) {
            const __half* qrow = qb + (size_t)(mt * 16 + g) * NPX + n0 + cpair;
            a[mt][0] = *(const uint32_t*)(qrow);
            a[mt][1] = *(const uint32_t*)(qrow + 8 * NPX);
            a[mt][2] = *(const uint32_t*)(qrow + 8);
            a[mt][3] = *(const uint32_t*)(qrow + 8 * NPX + 8);
        }
#pragma unroll
        for (int nt = 0; nt < 4; nt++) {
            const __half* krow = kb + (size_t)(nt * 8 + g) * NPX + n0 + cpair;
            bb[nt][0] = *(const uint32_t*)(krow);
            bb[nt][1] = *(const uint32_t*)(krow + 8);
        }
#pragma unroll
        for (int mt = 0; mt < 2; mt++)
#pragma unroll
            for (int nt = 0; nt < 4; nt++)
                mma_f16(acc[mt][nt], a[mt], bb[nt]);
    }
#pragma unroll
    for (int mt = 0; mt < 2; mt++)
#pragma unroll
        for (int nt = 0; nt < 4; nt++) {
            atomicAdd(&Gs[mt * 16 + g][nt * 8 + cpair],         acc[mt][nt][0]);
            atomicAdd(&Gs[mt * 16 + g][nt * 8 + cpair + 1],     acc[mt][nt][1]);
            atomicAdd(&Gs[mt * 16 + g + 8][nt * 8 + cpair],     acc[mt][nt][2]);
            atomicAdd(&Gs[mt * 16 + g + 8][nt * 8 + cpair + 1], acc[mt][nt][3]);
        }
    __syncthreads();
    for (int idx = tid; idx < 1024; idx += 256)
        atomicAdd(&g_G[(size_t)bh * 1024 + idx], Gs[idx >> 5][idx & 31]);
}

// ---------------------------------------------------------------------------
// K5: normalize gram -> 4 top-k masked softmaxes -> combined A, stored fp16.
// ---------------------------------------------------------------------------
__global__ void k5_softmax(const float* __restrict__ temp,
                           const float* __restrict__ a1p, const float* __restrict__ a2p,
                           const float* __restrict__ a3p, const float* __restrict__ a4p) {
    int bh = blockIdx.x;
    int h = bh % NHEADS;
    int tid = threadIdx.x;
    int warp = tid >> 5, d = tid & 31;
    float t = temp[h];
    float A1 = *a1p, A2 = *a2p, A3 = *a3p, A4 = *a4p;
    float rk = 1.f / fmaxf(sqrtf(g_sk[bh * CPH + d]), 1e-12f);
    for (int it = 0; it < 4; it++) {
        int c = warp * 4 + it;
        float rq = 1.f / fmaxf(sqrtf(g_sq[bh * CPH + c]), 1e-12f);
        float v = g_G[((size_t)bh * CPH + c) * CPH + d] * rq * rk * t;
        int rank = 0;
#pragma unroll
        for (int j = 0; j < 32; j++) {
            float vj = __shfl_sync(0xffffffffu, v, j);
            rank += (vj > v) || (vj == v && j < d);
        }
        float vmax = v;
#pragma unroll
        for (int o = 16; o; o >>= 1) vmax = fmaxf(vmax, __shfl_xor_sync(0xffffffffu, vmax, o));
        float e = expf(v - vmax);
        float e1 = rank < 16 ? e : 0.f;
        float e2 = rank < 21 ? e : 0.f;
        float e3 = rank < 24 ? e : 0.f;
        float e4 = rank < 25 ? e : 0.f;
#pragma unroll
        for (int o = 16; o; o >>= 1) {
            e1 += __shfl_xor_sync(0xffffffffu, e1, o);
            e2 += __shfl_xor_sync(0xffffffffu, e2, o);
            e3 += __shfl_xor_sync(0xffffffffu, e3, o);
            e4 += __shfl_xor_sync(0xffffffffu, e4, o);
        }
        float wgt = (rank < 16 ? A1 / e1 : 0.f) + (rank < 21 ? A2 / e2 : 0.f)
                  + (rank < 24 ? A3 / e3 : 0.f) + (rank < 25 ? A4 / e4 : 0.f);
        g_Ah[((size_t)bh * CPH + c) * CPH + d] = __float2half_rn(e * wgt);
    }
}

// ---------------------------------------------------------------------------
// K6: out_low = A @ v via fp16 MMA (A from global, v staged for ldsm.trans),
// exact GELU epilogue, fp16 g_low stores.
// ---------------------------------------------------------------------------
#define VS_PAD 264   // halves per v row (528B, 16B-aligned)
__global__ void __launch_bounds__(256) k6_mma() {
    const int pxb = blockIdx.x * 256;
    const int bh = blockIdx.y;
    const int b = bh / NHEADS, h = bh % NHEADS;
    const int tid = threadIdx.x;
    const int lane = tid & 31, warp = tid >> 5;
    const int g = lane >> 2, t4 = lane & 3;

    __shared__ __align__(16) __half vs[32][VS_PAD];
    uint32_t sbase;
    asm("{ .reg .u64 t; cvta.to.shared.u64 t, %1; cvt.u32.u64 %0, t; }"
        : "=r"(sbase) : "l"(vs));

    // stage v tile: 32 d x 256 n (coalesced rows)
    const __half* vb = g_Dh + (size_t)(b * C3 + 2 * DIM + h * CPH) * NPX + pxb;
    for (int idx = tid; idx < 32 * 32; idx += 256) {
        int d = idx >> 5, c8 = idx & 31;
        *(uint4*)&vs[d][c8 * 8] = *(const uint4*)&vb[(size_t)d * NPX + c8 * 8];
    }

    // A fragments straight from global (L1-resident, shared by 64 blocks)
    const __half* Ab = g_Ah + (size_t)bh * 1024;
    const int cpair = t4 * 2;
    uint32_t a[2][2][4];
#pragma unroll
    for (int kt = 0; kt < 2; kt++)
#pragma unroll
        for (int mt = 0; mt < 2; mt++) {
            const __half* ar = Ab + (mt * 16 + g) * 32 + kt * 16 + cpair;
            a[kt][mt][0] = *(const uint32_t*)(ar);
            a[kt][mt][1] = *(const uint32_t*)(ar + 8 * 32);
            a[kt][mt][2] = *(const uint32_t*)(ar + 8);
            a[kt][mt][3] = *(const uint32_t*)(ar + 8 * 32 + 8);
        }
    __syncthreads();

    const uint32_t bRow = sbase
        + (uint32_t)((lane & 7) + (((lane >> 3) & 1) << 3)) * (VS_PAD * 2)
        + (uint32_t)warp * 64;

    float acc[2][4][4];
#pragma unroll
    for (int i0 = 0; i0 < 2; i0++)
#pragma unroll
        for (int i1 = 0; i1 < 4; i1++)
#pragma unroll
            for (int i2 = 0; i2 < 4; i2++) acc[i0][i1][i2] = 0.f;

#pragma unroll
    for (int kt = 0; kt < 2; kt++)
#pragma unroll
        for (int nt = 0; nt < 4; nt++) {
            uint32_t bfr[2];
            ldsm2t(bfr, bRow + (uint32_t)kt * (16 * VS_PAD * 2) + nt * 16);
#pragma unroll
            for (int mt = 0; mt < 2; mt++)
                mma_f16(acc[mt][nt], a[kt][mt], bfr);
        }

    // GELU epilogue + half2 stores
    __half* ob = g_low + (size_t)(b * DIM + h * CPH) * NPX + pxb + warp * 32;
#pragma unroll
    for (int mt = 0; mt < 2; mt++) {
        const int c0 = mt * 16 + g;
#pragma unroll
        for (int nt = 0; nt < 4; nt++) {
            const int n = nt * 8 + 2 * t4;
            float x0 = acc[mt][nt][0], x1 = acc[mt][nt][1];
            float x2 = acc[mt][nt][2], x3 = acc[mt][nt][3];
            float g0 = 0.5f * x0 * (1.f + erff(x0 * 0.70710678118654752f));
            float g1 = 0.5f * x1 * (1.f + erff(x1 * 0.70710678118654752f));
            float g2 = 0.5f * x2 * (1.f + erff(x2 * 0.70710678118654752f));
            float g3 = 0.5f * x3 * (1.f + erff(x3 * 0.70710678118654752f));
            *(__half2*)&ob[(size_t)c0 * NPX + n] = __floats2half2_rn(g0, g1);
            *(__half2*)&ob[(size_t)(c0 + 8) * NPX + n] = __floats2half2_rn(g2, g3);
        }
    }
}

extern "C" void kernel_launch(void* const* d_in, const int* in_sizes, int n_in,
                              void* d_out, int out_size) {
    const float* x      = (const float*)d_in[0];
    const float* temp   = (const float*)d_in[1];
    const float* qkv_w  = (const float*)d_in[2];
    const float* dw_w   = (const float*)d_in[3];
    const float* proj_w = (const float*)d_in[4];
    const float* a1     = (const float*)d_in[5];
    const float* a2     = (const float*)d_in[6];
    const float* a3     = (const float*)d_in[7];
    const float* a4     = (const float*)d_in[8];
    float* out = (float*)d_out;

    cudaFuncSetAttribute(k1_mma, cudaFuncAttributeMaxDynamicSharedMemorySize, K1_SMEM);
    cudaFuncSetAttribute(k7_mma, cudaFuncAttributeMaxDynamicSharedMemorySize, K7_SMEM);

    k_init<<<96, 256>>>();
    k0_convert<<<144, 256>>>(qkv_w, proj_w);
    k1_mma<<<dim3(512, 1, 4), 256, K1_SMEM>>>(x);
    k2_dw<<<dim3(4, 576, 4), 256>>>(dw_w);
    k4_mma<<<dim3(32, 24), 256>>>();
    k5_softmax<<<24, 256>>>(temp, a1, a2, a3, a4);
    k6_mma<<<dim3(64, 24), 256>>>();
    k7_mma<<<dim3(128, 1, 4), 256, K7_SMEM>>>(out);
}